// round 12
// baseline (speedup 1.0000x reference)
#include <cuda_runtime.h>
#include <cuda_fp16.h>
#include <math.h>
#include <cstdint>

// Problem constants
#define B_     16
#define T_     4096
#define KF     1024
#define DIN    512
#define DM     256
#define DOUT   256
#define NL     2
#define DS     16
#define DCONV  4
#define DI     512
#define DTR    16
#define NT     (B_*KF)   // 16384 tokens

// fp16 weight buffer offsets (in halves)
#define WH_IP    0                          // w_ip: 256*512
#define WH_IN    (WH_IP + DM*DIN)           // W_in: 2*1024*256
#define WH_XP    (WH_IN + NL*2*DI*DM)       // W_xp: 2*48*512
#define WH_OUT   (WH_XP + NL*48*DI)         // W_out: 2*256*512
#define WH_TOTAL (WH_OUT + NL*DM*DI)

// ---------------- scratch (device globals; no runtime alloc) ----------------
__device__ float  g_x  [(size_t)NT*DM];       // residual stream (fp32)
__device__ __half g_xn [(size_t)NT*DM];       // layernorm output
__device__ __half g_xz [(size_t)NT*2*DI];     // in-projection (xp | z)
__device__ __half g_xc [(size_t)NT*DI];       // conv+silu output
__device__ float  g_dbl[(size_t)NT*48];       // dt_low(16) | Bm(16) | Cm(16)
__device__ __half g_dt [(size_t)NT*DI];       // softplus(dt), fp16
__device__ __half g_y  [(size_t)NT*DI];       // scan output (gated)
__device__ float  g_redp[(size_t)B_*16*DM];   // partial masked sums
__device__ __half g_wh [(size_t)WH_TOTAL];    // fp16 weights

// ---------------------------- helpers ---------------------------------------
__device__ __forceinline__ void mma_fp16(float* d, const uint32_t* a,
                                         const uint32_t* b) {
    asm volatile(
        "mma.sync.aligned.m16n8k16.row.col.f32.f16.f16.f32 "
        "{%0,%1,%2,%3}, {%4,%5,%6,%7}, {%8,%9}, {%0,%1,%2,%3};"
        : "+f"(d[0]), "+f"(d[1]), "+f"(d[2]), "+f"(d[3])
        : "r"(a[0]), "r"(a[1]), "r"(a[2]), "r"(a[3]),
          "r"(b[0]), "r"(b[1]));
}

__device__ __forceinline__ void ldmatrix_x4(uint32_t& r0, uint32_t& r1,
                                            uint32_t& r2, uint32_t& r3,
                                            uint32_t addr) {
    asm volatile(
        "ldmatrix.sync.aligned.m8n8.x4.shared.b16 {%0,%1,%2,%3}, [%4];"
        : "=r"(r0), "=r"(r1), "=r"(r2), "=r"(r3) : "r"(addr));
}

__device__ __forceinline__ uint32_t pack_half2(float lo, float hi) {
    __half2 h = __floats2half2_rn(lo, hi);
    return *reinterpret_cast<uint32_t*>(&h);
}

// ---------------- flat f32 -> f16 conversion --------------------------------
__global__ void f2h_kernel(const float* __restrict__ src,
                           __half* __restrict__ dst, int n)
{
    int i = (blockIdx.x * 256 + threadIdx.x) * 4;
    if (i < n) {
        float4 v = *reinterpret_cast<const float4*>(src + i);
        uint2 u = make_uint2(pack_half2(v.x, v.y), pack_half2(v.z, v.w));
        *reinterpret_cast<uint2*>(dst + i) = u;
    }
}

// =================== fp16 mma.sync GEMM: C = A @ W^T ========================
// CTA tile 128 x NTILE, 8 warps (WM x WN), K chunked by 32, ldmatrix fragments.
// AMODE: 1 = gather fp32 feats, 2 = fp16 A (direct). W is fp16 (direct).
template<int NTILE, int WN, int AMODE, bool BIAS, bool RESID, bool OUTHALF>
__global__ __launch_bounds__(256, 2)
void gemm_h(const __half* __restrict__ Ah, const __half* __restrict__ Wh,
            float* __restrict__ Cf, __half* __restrict__ Ch, int N, int Kd,
            const float* __restrict__ bias, const float* __restrict__ resid,
            const float* __restrict__ feats, const int* __restrict__ idx)
{
    constexpr int WM = 8 / WN;
    constexpr int RM = 128 / WM;
    constexpr int RN = NTILE / WN;
    constexpr int mM = RM / 16;
    constexpr int mN = RN / 8;
    constexpr int mNP = mN / 2;                  // B ldmatrix pairs
    constexpr int SA = 40;                       // halves per row (80 B)
    constexpr int BQ = NTILE * 4;                // B uint4 loads (8 halves each)

    __shared__ __half sA[2][128 * SA];
    __shared__ __half sB[2][NTILE * SA];
    __shared__ int rowoff[128];

    const int tid  = threadIdx.x;
    const int warp = tid >> 5, lane = tid & 31;
    const int g    = lane >> 2, t = lane & 3;
    const int wm   = warp % WM, wn = warp / WM;
    const int m0   = blockIdx.y * 128, n0 = blockIdx.x * NTILE;

    if (AMODE == 1) {
        if (tid < 128) {
            int tok = m0 + tid;
            rowoff[tid] = (tok >> 10) * T_ + idx[tok];
        }
        __syncthreads();
    }

    const uint32_t sAu = (uint32_t)__cvta_generic_to_shared(&sA[0][0]);
    const uint32_t sBu = (uint32_t)__cvta_generic_to_shared(&sB[0][0]);

    float4 arf[4];
    uint4  arh[2];
    uint4  brh;
    bool   bact = (BQ % 256 == 0) || (tid < BQ);

    auto ldA = [&](int k0) {
        if (AMODE == 2) {
            #pragma unroll
            for (int j = 0; j < 2; ++j) {
                int it = tid + 256 * j;
                int r = it >> 2, q = it & 3;
                arh[j] = *reinterpret_cast<const uint4*>(
                    Ah + (size_t)(m0 + r) * Kd + k0 + q * 8);
            }
        } else {
            #pragma unroll
            for (int j = 0; j < 4; ++j) {
                int it = tid + 256 * j;
                int r = it >> 3, q = it & 7;
                arf[j] = *reinterpret_cast<const float4*>(
                    feats + (size_t)rowoff[r] * Kd + k0 + q * 4);
            }
        }
    };
    auto ldB = [&](int k0) {
        if (bact) {
            int r = tid >> 2, q = tid & 3;
            brh = *reinterpret_cast<const uint4*>(
                Wh + (size_t)(n0 + r) * Kd + k0 + q * 8);
        }
    };
    auto stA = [&](int buf) {
        if (AMODE == 2) {
            #pragma unroll
            for (int j = 0; j < 2; ++j) {
                int it = tid + 256 * j;
                int r = it >> 2, q = it & 3;
                *reinterpret_cast<uint4*>(&sA[buf][r * SA + q * 8]) = arh[j];
            }
        } else {
            #pragma unroll
            for (int j = 0; j < 4; ++j) {
                int it = tid + 256 * j;
                int r = it >> 3, q = it & 7;
                uint2 u = make_uint2(pack_half2(arf[j].x, arf[j].y),
                                     pack_half2(arf[j].z, arf[j].w));
                *reinterpret_cast<uint2*>(&sA[buf][r * SA + q * 4]) = u;
            }
        }
    };
    auto stB = [&](int buf) {
        if (bact) {
            int r = tid >> 2, q = tid & 3;
            *reinterpret_cast<uint4*>(&sB[buf][r * SA + q * 8]) = brh;
        }
    };

    float acc[mM][mN][4];
    #pragma unroll
    for (int i = 0; i < mM; ++i)
        #pragma unroll
        for (int j = 0; j < mN; ++j)
            #pragma unroll
            for (int q = 0; q < 4; ++q) acc[i][j][q] = 0.f;

    // ldmatrix lane-address components (in halves)
    const int a_row  = (lane & 15);
    const int a_koff = (lane >> 4) << 3;
    const int b_nrow = (lane & 7);
    const int b_tile = (lane >> 4);
    const int b_koff = ((lane >> 3) & 1) << 3;

    const int nc = Kd >> 5;
    ldA(0); ldB(0);
    stA(0); stB(0);
    __syncthreads();

    for (int i = 0; i < nc; ++i) {
        const int buf = i & 1;
        if (i + 1 < nc) { ldA((i + 1) << 5); ldB((i + 1) << 5); }

        const uint32_t bAu = sAu + (uint32_t)buf * (128 * SA * 2);
        const uint32_t bBu = sBu + (uint32_t)buf * (NTILE * SA * 2);
        #pragma unroll
        for (int kk = 0; kk < 32; kk += 16) {
            uint32_t afr[mM][4];
            #pragma unroll
            for (int i2 = 0; i2 < mM; ++i2) {
                int rb = wm * RM + i2 * 16;
                uint32_t addr = bAu +
                    (uint32_t)((rb + a_row) * SA + kk + a_koff) * 2;
                ldmatrix_x4(afr[i2][0], afr[i2][1], afr[i2][2], afr[i2][3],
                            addr);
            }
            uint32_t bfr[mN][2];
            #pragma unroll
            for (int jp = 0; jp < mNP; ++jp) {
                int cb = wn * RN + jp * 16;
                uint32_t addr = bBu +
                    (uint32_t)((cb + b_tile * 8 + b_nrow) * SA + kk + b_koff) * 2;
                ldmatrix_x4(bfr[2*jp][0], bfr[2*jp][1],
                            bfr[2*jp+1][0], bfr[2*jp+1][1], addr);
            }
            #pragma unroll
            for (int i2 = 0; i2 < mM; ++i2)
                #pragma unroll
                for (int j2 = 0; j2 < mN; ++j2)
                    mma_fp16(acc[i2][j2], afr[i2], bfr[j2]);
        }

        if (i + 1 < nc) { stA(buf ^ 1); stB(buf ^ 1); __syncthreads(); }
    }

    // epilogue
    #pragma unroll
    for (int i2 = 0; i2 < mM; ++i2) {
        #pragma unroll
        for (int j2 = 0; j2 < mN; ++j2) {
            int row = m0 + wm * RM + i2 * 16 + g;
            int col = n0 + wn * RN + j2 * 8 + t * 2;
            float v0 = acc[i2][j2][0], v1 = acc[i2][j2][1];
            float v2 = acc[i2][j2][2], v3 = acc[i2][j2][3];
            if (BIAS) {
                float bc0 = bias[col], bc1 = bias[col + 1];
                v0 += bc0; v1 += bc1; v2 += bc0; v3 += bc1;
            }
            if (RESID) {
                v0 += resid[(size_t)row * N + col];
                v1 += resid[(size_t)row * N + col + 1];
                v2 += resid[(size_t)(row + 8) * N + col];
                v3 += resid[(size_t)(row + 8) * N + col + 1];
            }
            if (OUTHALF) {
                *reinterpret_cast<__half2*>(&Ch[(size_t)row * N + col]) =
                    __floats2half2_rn(v0, v1);
                *reinterpret_cast<__half2*>(&Ch[(size_t)(row + 8) * N + col]) =
                    __floats2half2_rn(v2, v3);
            } else {
                *reinterpret_cast<float2*>(&Cf[(size_t)row * N + col]) =
                    make_float2(v0, v1);
                *reinterpret_cast<float2*>(&Cf[(size_t)(row + 8) * N + col]) =
                    make_float2(v2, v3);
            }
        }
    }
}

// ---------- LayerNorm, warp-per-token (8 floats/lane, shfl-only) -------------
__global__ void ln_kernel(const float* __restrict__ x,
                          const float* __restrict__ gam,
                          const float* __restrict__ bet,
                          __half* __restrict__ xn)
{
    const int tok  = (blockIdx.x * blockDim.x + threadIdx.x) >> 5;
    const int lane = threadIdx.x & 31;
    const float* row = x + (size_t)tok * DM + lane * 8;

    float4 v0 = *reinterpret_cast<const float4*>(row);
    float4 v1 = *reinterpret_cast<const float4*>(row + 4);

    float s = v0.x + v0.y + v0.z + v0.w + v1.x + v1.y + v1.z + v1.w;
    #pragma unroll
    for (int o = 16; o; o >>= 1) s += __shfl_xor_sync(0xffffffffu, s, o);
    const float mu = s * (1.0f / DM);

    float d0 = v0.x - mu, d1 = v0.y - mu, d2 = v0.z - mu, d3 = v0.w - mu;
    float d4 = v1.x - mu, d5 = v1.y - mu, d6 = v1.z - mu, d7 = v1.w - mu;
    float q = d0*d0 + d1*d1 + d2*d2 + d3*d3 + d4*d4 + d5*d5 + d6*d6 + d7*d7;
    #pragma unroll
    for (int o = 16; o; o >>= 1) q += __shfl_xor_sync(0xffffffffu, q, o);
    const float rs = rsqrtf(q * (1.0f / DM) + 1e-5f);

    float4 g0 = *reinterpret_cast<const float4*>(gam + lane * 8);
    float4 g1 = *reinterpret_cast<const float4*>(gam + lane * 8 + 4);
    float4 b0 = *reinterpret_cast<const float4*>(bet + lane * 8);
    float4 b1 = *reinterpret_cast<const float4*>(bet + lane * 8 + 4);

    uint4 o4;
    *reinterpret_cast<__half2*>(&o4.x) =
        __floats2half2_rn(d0*rs*g0.x + b0.x, d1*rs*g0.y + b0.y);
    *reinterpret_cast<__half2*>(&o4.y) =
        __floats2half2_rn(d2*rs*g0.z + b0.z, d3*rs*g0.w + b0.w);
    *reinterpret_cast<__half2*>(&o4.z) =
        __floats2half2_rn(d4*rs*g1.x + b1.x, d5*rs*g1.y + b1.y);
    *reinterpret_cast<__half2*>(&o4.w) =
        __floats2half2_rn(d6*rs*g1.z + b1.z, d7*rs*g1.w + b1.w);
    *reinterpret_cast<uint4*>(xn + (size_t)tok * DM + lane * 8) = o4;
}

// ------- causal depthwise conv (width 4) + SiLU, fp16 in/out ----------------
__global__ void conv_kernel(const __half* __restrict__ xz,
                            const float* __restrict__ cw,
                            const float* __restrict__ cb,
                            __half* __restrict__ xc)
{
    int gi = blockIdx.x * 256 + threadIdx.x;  // over (NT/2)*(DI/4)
    if (gi >= (NT/2)*(DI/4)) return;
    int d4 = (gi & 127) << 2;
    int th = gi >> 7;
    int t0 = th << 1;
    int k0 = t0 & (KF-1);

    float4 w0 = *reinterpret_cast<const float4*>(cw + (d4+0)*4);
    float4 w1 = *reinterpret_cast<const float4*>(cw + (d4+1)*4);
    float4 w2 = *reinterpret_cast<const float4*>(cw + (d4+2)*4);
    float4 w3 = *reinterpret_cast<const float4*>(cw + (d4+3)*4);
    const float wj[4][4] = {
        {w0.x, w1.x, w2.x, w3.x},
        {w0.y, w1.y, w2.y, w3.y},
        {w0.z, w1.z, w2.z, w3.z},
        {w0.w, w1.w, w2.w, w3.w}};
    float4 bias4 = *reinterpret_cast<const float4*>(cb + d4);

    float4 tap[5];
    #pragma unroll
    for (int j = 0; j < 5; ++j) {
        int kk = k0 - 3 + j;
        if (kk >= 0) {
            uint2 u = *reinterpret_cast<const uint2*>(
                xz + (size_t)(t0 - 3 + j) * (2*DI) + d4);
            float2 f0 = __half22float2(*reinterpret_cast<__half2*>(&u.x));
            float2 f1 = __half22float2(*reinterpret_cast<__half2*>(&u.y));
            tap[j] = make_float4(f0.x, f0.y, f1.x, f1.y);
        } else {
            tap[j] = make_float4(0.f, 0.f, 0.f, 0.f);
        }
    }

    float4 a0 = bias4, a1 = bias4;
    #pragma unroll
    for (int j = 0; j < 4; ++j) {
        a0.x += wj[j][0] * tap[j].x;   a1.x += wj[j][0] * tap[j+1].x;
        a0.y += wj[j][1] * tap[j].y;   a1.y += wj[j][1] * tap[j+1].y;
        a0.z += wj[j][2] * tap[j].z;   a1.z += wj[j][2] * tap[j+1].z;
        a0.w += wj[j][3] * tap[j].w;   a1.w += wj[j][3] * tap[j+1].w;
    }
    float4 o0, o1;
    o0.x = a0.x / (1.f + __expf(-a0.x));  o1.x = a1.x / (1.f + __expf(-a1.x));
    o0.y = a0.y / (1.f + __expf(-a0.y));  o1.y = a1.y / (1.f + __expf(-a1.y));
    o0.z = a0.z / (1.f + __expf(-a0.z));  o1.z = a1.z / (1.f + __expf(-a1.z));
    o0.w = a0.w / (1.f + __expf(-a0.w));  o1.w = a1.w / (1.f + __expf(-a1.w));

    uint2 s0, s1;
    *reinterpret_cast<__half2*>(&s0.x) = __floats2half2_rn(o0.x, o0.y);
    *reinterpret_cast<__half2*>(&s0.y) = __floats2half2_rn(o0.z, o0.w);
    *reinterpret_cast<__half2*>(&s1.x) = __floats2half2_rn(o1.x, o1.y);
    *reinterpret_cast<__half2*>(&s1.y) = __floats2half2_rn(o1.z, o1.w);
    *reinterpret_cast<uint2*>(xc + (size_t)t0*DI + d4)     = s0;
    *reinterpret_cast<uint2*>(xc + (size_t)(t0+1)*DI + d4) = s1;
}

// ------- dt = softplus(dbl[:, :16] @ W_dt^T + b_dt) -> fp16 ------------------
__global__ void dt_kernel(const float* __restrict__ dbl,
                          const float* __restrict__ Wdt,
                          const float* __restrict__ bdt,
                          __half* __restrict__ dtout)
{
    __shared__ float s_dbl[64 * 16];
    const int tid = threadIdx.x;      // 256
    const int t0  = blockIdx.x * 64;

    float w0[16], w1[16];
    #pragma unroll
    for (int r = 0; r < 16; ++r) {
        w0[r] = Wdt[tid * 16 + r];
        w1[r] = Wdt[(tid + 256) * 16 + r];
    }
    const float b0 = bdt[tid], b1 = bdt[tid + 256];

    for (int i = tid; i < 64 * 16; i += 256) {
        int tt = i >> 4, r = i & 15;
        s_dbl[i] = dbl[(size_t)(t0 + tt) * 48 + r];
    }
    __syncthreads();

    for (int tt = 0; tt < 64; ++tt) {
        float a0 = b0, a1 = b1;
        #pragma unroll
        for (int r = 0; r < 16; ++r) {
            float v = s_dbl[tt * 16 + r];
            a0 += v * w0[r];
            a1 += v * w1[r];
        }
        size_t t = (size_t)(t0 + tt) * DI;
        float r0 = (a0 > 20.f) ? a0 : __logf(1.f + __expf(a0));
        float r1 = (a1 > 20.f) ? a1 : __logf(1.f + __expf(a1));
        dtout[t + tid]       = __float2half_rn(r0);
        dtout[t + tid + 256] = __float2half_rn(r1);
    }
}

// ---- selective scan: 8 lanes per d (2 states/lane), unroll 4, prefetch 4 ----
__global__ void scan_kernel(const __half* __restrict__ dt,
                            const __half* __restrict__ xc,
                            const float* __restrict__ dbl,
                            const __half* __restrict__ xz,
                            const float* __restrict__ Al,
                            const float* __restrict__ Dp,
                            __half* __restrict__ y)
{
    const int warp_gid = (blockIdx.x * blockDim.x + threadIdx.x) >> 5; // 0..2047
    const int lane = threadIdx.x & 31;
    const int g = lane >> 3;
    const int q = lane & 7;
    const int b = warp_gid >> 7;
    const int d = ((warp_gid & 127) << 2) + g;

    const float a0 = -__expf(Al[d*DS + 2*q + 0]);
    const float a1 = -__expf(Al[d*DS + 2*q + 1]);
    const float dp = Dp[d];

    bool fastl = fabsf(a0 + (float)(2*q+1)) < 1e-4f * (2*q+1)
              && fabsf(a1 + (float)(2*q+2)) < 1e-4f * (2*q+2);
    const bool fast = __all_sync(0xffffffffu, fastl);

    float h0 = 0.f, h1 = 0.f;
    const size_t tb = (size_t)b * KF;

    float  dtv[4], xcv[4], zv[4];
    float2 bm[4], cm[4];
    #pragma unroll
    for (int j = 0; j < 4; ++j) {
        const size_t t = tb + j;
        dtv[j] = __half2float(dt[t*DI + d]);
        xcv[j] = __half2float(xc[t*DI + d]);
        zv[j]  = __half2float(xz[t*(2*DI) + DI + d]);
        bm[j]  = *reinterpret_cast<const float2*>(dbl + t*48 + 16 + 2*q);
        cm[j]  = *reinterpret_cast<const float2*>(dbl + t*48 + 32 + 2*q);
    }

    for (int k = 0; k < KF; k += 4) {
        float  dtn[4], xcn[4], zvn[4];
        float2 bmn[4], cmn[4];
        #pragma unroll
        for (int j = 0; j < 4; ++j) {
            int kk = k + 4 + j; if (kk > KF-1) kk = KF-1;
            const size_t t = tb + kk;
            dtn[j] = __half2float(dt[t*DI + d]);
            xcn[j] = __half2float(xc[t*DI + d]);
            zvn[j] = __half2float(xz[t*(2*DI) + DI + d]);
            bmn[j] = *reinterpret_cast<const float2*>(dbl + t*48 + 16 + 2*q);
            cmn[j] = *reinterpret_cast<const float2*>(dbl + t*48 + 32 + 2*q);
        }

        float E[4];
        if (fast) {
            #pragma unroll
            for (int j = 0; j < 4; ++j) E[j] = __expf(-dtv[j]);
        }

        #pragma unroll
        for (int j = 0; j < 4; ++j) {
            float p0, p1;
            if (fast) {
                float e = E[j];
                float b2 = e*e;
                float b4 = b2*b2;
                float b8 = b4*b4;
                float pw = e;
                if (q & 1) pw *= b2;
                if (q & 2) pw *= b4;
                if (q & 4) pw *= b8;
                p0 = pw;
                p1 = pw * e;
            } else {
                p0 = __expf(dtv[j]*a0);
                p1 = __expf(dtv[j]*a1);
            }
            const float dtx = dtv[j] * xcv[j];
            h0 = p0*h0 + dtx*bm[j].x;
            h1 = p1*h1 + dtx*bm[j].y;
            float yp = h0*cm[j].x + h1*cm[j].y;
            yp += __shfl_xor_sync(0xffffffffu, yp, 1);
            yp += __shfl_xor_sync(0xffffffffu, yp, 2);
            yp += __shfl_xor_sync(0xffffffffu, yp, 4);
            if (q == 0) {
                float zs = zv[j] / (1.f + __expf(-zv[j]));
                y[(tb + k + j)*DI + d] = __float2half_rn((yp + dp*xcv[j]) * zs);
            }
        }
        #pragma unroll
        for (int j = 0; j < 4; ++j) {
            dtv[j] = dtn[j]; xcv[j] = xcn[j]; zv[j] = zvn[j];
            bm[j] = bmn[j]; cm[j] = cmn[j];
        }
    }
}

// ---------------- masked partial reduction over K ---------------------------
__global__ void reduce_kernel(const float* __restrict__ x,
                              const unsigned char* __restrict__ mask,
                              float* __restrict__ redp)
{
    const int b  = blockIdx.x;
    const int ch = blockIdx.y;
    const int m  = threadIdx.x;
    float acc = 0.f;
    const int kbeg = ch * 64;
    #pragma unroll 4
    for (int k = kbeg; k < kbeg + 64; ++k) {
        if (!mask[b*KF + k])
            acc += x[((size_t)b*KF + k)*DM + m];
    }
    redp[((size_t)b*16 + ch)*DM + m] = acc;
}

// ---------------- combine partials + output projection + mean ---------------
__global__ void final_kernel(const float* __restrict__ redp,
                             const unsigned char* __restrict__ mask,
                             const float* __restrict__ w_op,
                             const float* __restrict__ b_op,
                             float* __restrict__ out)
{
    const int b = blockIdx.x;
    const int o = threadIdx.x;
    __shared__ float s_r[DM];
    __shared__ int s_cnt;

    if (o == 0) s_cnt = 0;
    __syncthreads();

    int c = 0;
    #pragma unroll 4
    for (int k = o; k < KF; k += 256) c += mask[b*KF + k] ? 0 : 1;
    atomicAdd(&s_cnt, c);

    float acc = 0.f;
    #pragma unroll
    for (int ch = 0; ch < 16; ++ch) acc += redp[((size_t)b*16 + ch)*DM + o];
    s_r[o] = acc;
    __syncthreads();

    float cnt = fmaxf((float)s_cnt, 1.0f);
    float dot = 0.f;
    #pragma unroll 4
    for (int m = 0; m < DM; ++m) dot += s_r[m] * w_op[o*DM + m];
    out[(size_t)b*DOUT + o] = dot / cnt + b_op[o];
}

// ---------------- launch ----------------------------------------------------
extern "C" void kernel_launch(void* const* d_in, const int* in_sizes, int n_in,
                              void* d_out, int out_size)
{
    const float*         feats  = (const float*)d_in[0];
    const int*           idx    = (const int*)d_in[1];
    const unsigned char* mask   = (const unsigned char*)d_in[2];
    const float* w_ip   = (const float*)d_in[3];
    const float* b_ip   = (const float*)d_in[4];
    const float* ln_g   = (const float*)d_in[5];
    const float* ln_b   = (const float*)d_in[6];
    const float* W_in   = (const float*)d_in[7];
    const float* conv_w = (const float*)d_in[8];
    const float* conv_b = (const float*)d_in[9];
    const float* W_xp   = (const float*)d_in[10];
    const float* W_dt   = (const float*)d_in[11];
    const float* b_dt   = (const float*)d_in[12];
    const float* A_log  = (const float*)d_in[13];
    const float* Dp     = (const float*)d_in[14];
    const float* W_out  = (const float*)d_in[15];
    const float* w_op   = (const float*)d_in[16];
    const float* b_op   = (const float*)d_in[17];
    float* out = (float*)d_out;

    float *x, *dbl, *redp;
    __half *xn, *xz, *xc, *dt, *y, *wh;
    cudaGetSymbolAddress((void**)&x,    g_x);
    cudaGetSymbolAddress((void**)&xn,   g_xn);
    cudaGetSymbolAddress((void**)&xz,   g_xz);
    cudaGetSymbolAddress((void**)&xc,   g_xc);
    cudaGetSymbolAddress((void**)&dbl,  g_dbl);
    cudaGetSymbolAddress((void**)&dt,   g_dt);
    cudaGetSymbolAddress((void**)&y,    g_y);
    cudaGetSymbolAddress((void**)&redp, g_redp);
    cudaGetSymbolAddress((void**)&wh,   g_wh);

    // --- pre-convert all GEMM weights to fp16 (counts are multiples of 4) ---
    f2h_kernel<<<(DM*DIN/4 + 255)/256, 256>>>(w_ip, wh + WH_IP, DM*DIN);
    f2h_kernel<<<(NL*2*DI*DM/4 + 255)/256, 256>>>(W_in, wh + WH_IN, NL*2*DI*DM);
    f2h_kernel<<<(NL*48*DI/4 + 255)/256, 256>>>(W_xp, wh + WH_XP, NL*48*DI);
    f2h_kernel<<<(NL*DM*DI/4 + 255)/256, 256>>>(W_out, wh + WH_OUT, NL*DM*DI);

    // input projection with fused keyframe gather: x (fp32)
    gemm_h<64, 2, 1, true, false, false><<<dim3(DM/64, NT/128), 256>>>(
        nullptr, wh + WH_IP, x, nullptr, DM, DIN,
        b_ip, nullptr, feats, idx);

    for (int l = 0; l < NL; ++l) {
        ln_kernel<<<NT/8, 256>>>(x, ln_g + l*DM, ln_b + l*DM, xn);

        // xz = xn @ W_in^T  (fp16 in/out, fp16 weights)
        gemm_h<64, 2, 2, false, false, true>
            <<<dim3(2*DI/64, NT/128), 256>>>(
            xn, wh + WH_IN + (size_t)l*2*DI*DM, nullptr, xz, 2*DI, DM,
            nullptr, nullptr, nullptr, nullptr);

        conv_kernel<<<((NT/2)*(DI/4))/256, 256>>>(
            xz, conv_w + (size_t)l*DI*DCONV, conv_b + (size_t)l*DI, xc);

        // dbl = xc @ W_xp^T  (fp16 in, fp32 out), N=48
        gemm_h<48, 1, 2, false, false, false>
            <<<dim3(1, NT/128), 256>>>(
            xc, wh + WH_XP + (size_t)l*48*DI, dbl, nullptr, 48, DI,
            nullptr, nullptr, nullptr, nullptr);

        // dt = softplus(dbl[:, :16] @ W_dt^T + b_dt) -> fp16
        dt_kernel<<<NT/64, 256>>>(
            dbl, W_dt + (size_t)l*DI*DTR, b_dt + (size_t)l*DI, dt);

        // scan: 2048 warps = 256 blocks x 256 threads
        scan_kernel<<<256, 256>>>(
            dt, xc, dbl, xz, A_log + (size_t)l*DI*DS, Dp + (size_t)l*DI, y);

        // x = y @ W_out^T + x  (fp16 A/weights, fp32 resid/out)
        gemm_h<64, 2, 2, false, true, false>
            <<<dim3(DM/64, NT/128), 256>>>(
            y, wh + WH_OUT + (size_t)l*DM*DI, x, nullptr, DM, DI,
            nullptr, x, nullptr, nullptr);
    }

    reduce_kernel<<<dim3(B_, 16), 256>>>(x, mask, redp);
    final_kernel<<<B_, 256>>>(redp, mask, w_op, b_op, out);
}

// round 13
// speedup vs baseline: 1.0858x; 1.0858x over previous
#include <cuda_runtime.h>
#include <cuda_fp16.h>
#include <math.h>
#include <cstdint>

// Problem constants
#define B_     16
#define T_     4096
#define KF     1024
#define DIN    512
#define DM     256
#define DOUT   256
#define NL     2
#define DS     16
#define DCONV  4
#define DI     512
#define DTR    16
#define NT     (B_*KF)   // 16384 tokens

// fp16 weight buffer offsets (in halves)
#define WHN_IP   (DM*DIN)            // 131072
#define WHN_IN   (NL*2*DI*DM)        // 524288
#define WHN_XP   (NL*48*DI)          // 49152
#define WHN_OUT  (NL*DM*DI)          // 262144
#define WH_IP    0
#define WH_IN    (WH_IP + WHN_IP)
#define WH_XP    (WH_IN + WHN_IN)
#define WH_OUT   (WH_XP + WHN_XP)
#define WH_TOTAL (WH_OUT + WHN_OUT)  // 966656

// ---------------- scratch (device globals; no runtime alloc) ----------------
__device__ float  g_x  [(size_t)NT*DM];       // residual stream (fp32)
__device__ __half g_xn [(size_t)NT*DM];       // layernorm output
__device__ __half g_xz [(size_t)NT*2*DI];     // in-projection (xp | z)
__device__ __half g_xc [(size_t)NT*DI];       // conv+silu output
__device__ float  g_dbl[(size_t)NT*48];       // dt_low(16) | Bm(16) | Cm(16)
__device__ __half g_dt [(size_t)NT*DI];       // softplus(dt), fp16
__device__ __half g_y  [(size_t)NT*DI];       // scan output (gated)
__device__ float  g_redp[(size_t)B_*16*DM];   // partial masked sums
__device__ __half g_wh [(size_t)WH_TOTAL];    // fp16 weights

// ---------------------------- helpers ---------------------------------------
__device__ __forceinline__ void mma_fp16(float* d, const uint32_t* a,
                                         const uint32_t* b) {
    asm volatile(
        "mma.sync.aligned.m16n8k16.row.col.f32.f16.f16.f32 "
        "{%0,%1,%2,%3}, {%4,%5,%6,%7}, {%8,%9}, {%0,%1,%2,%3};"
        : "+f"(d[0]), "+f"(d[1]), "+f"(d[2]), "+f"(d[3])
        : "r"(a[0]), "r"(a[1]), "r"(a[2]), "r"(a[3]),
          "r"(b[0]), "r"(b[1]));
}

__device__ __forceinline__ void ldmatrix_x4(uint32_t& r0, uint32_t& r1,
                                            uint32_t& r2, uint32_t& r3,
                                            uint32_t addr) {
    asm volatile(
        "ldmatrix.sync.aligned.m8n8.x4.shared.b16 {%0,%1,%2,%3}, [%4];"
        : "=r"(r0), "=r"(r1), "=r"(r2), "=r"(r3) : "r"(addr));
}

__device__ __forceinline__ uint32_t pack_half2(float lo, float hi) {
    __half2 h = __floats2half2_rn(lo, hi);
    return *reinterpret_cast<uint32_t*>(&h);
}

// -------- single-launch f32 -> f16 conversion of all GEMM weights -----------
__global__ void f2h_all_kernel(const float* __restrict__ w_ip,
                               const float* __restrict__ W_in,
                               const float* __restrict__ W_xp,
                               const float* __restrict__ W_out,
                               __half* __restrict__ dst)
{
    int i = (blockIdx.x * 256 + threadIdx.x) * 4;
    if (i >= WH_TOTAL) return;
    const float* src;
    int off;
    if (i < WH_IN)        { src = w_ip;  off = i - WH_IP;  }
    else if (i < WH_XP)   { src = W_in;  off = i - WH_IN;  }
    else if (i < WH_OUT)  { src = W_xp;  off = i - WH_XP;  }
    else                  { src = W_out; off = i - WH_OUT; }
    float4 v = *reinterpret_cast<const float4*>(src + off);
    uint2 u = make_uint2(pack_half2(v.x, v.y), pack_half2(v.z, v.w));
    *reinterpret_cast<uint2*>(dst + i) = u;
}

// =================== fp16 mma.sync GEMM: C = A @ W^T ========================
// CTA tile 128 x NTILE, 8 warps (WM x WN), K chunked by 64, ldmatrix fragments.
// AMODE: 1 = gather fp32 feats, 2 = fp16 A (direct). W is fp16 (direct).
template<int NTILE, int WN, int AMODE, bool BIAS, bool RESID, bool OUTHALF>
__global__ __launch_bounds__(256, 2)
void gemm_h(const __half* __restrict__ Ah, const __half* __restrict__ Wh,
            float* __restrict__ Cf, __half* __restrict__ Ch, int N, int Kd,
            const float* __restrict__ bias, const float* __restrict__ resid,
            const float* __restrict__ feats, const int* __restrict__ idx)
{
    constexpr int WM = 8 / WN;
    constexpr int RM = 128 / WM;
    constexpr int RN = NTILE / WN;
    constexpr int mM = RM / 16;
    constexpr int mN = RN / 8;
    constexpr int mNP = mN / 2;
    constexpr int KC = 64;                       // K chunk (halves)
    constexpr int SA = 72;                       // halves per row (144 B)
    constexpr int BQ = NTILE * 8;                // B uint4 per chunk

    __shared__ __half sA[2][128 * SA];
    __shared__ __half sB[2][NTILE * SA];
    __shared__ int rowoff[128];

    const int tid  = threadIdx.x;
    const int warp = tid >> 5, lane = tid & 31;
    const int g    = lane >> 2, t = lane & 3;
    const int wm   = warp % WM, wn = warp / WM;
    const int m0   = blockIdx.y * 128, n0 = blockIdx.x * NTILE;

    if (AMODE == 1) {
        if (tid < 128) {
            int tok = m0 + tid;
            rowoff[tid] = (tok >> 10) * T_ + idx[tok];
        }
        __syncthreads();
    }

    const uint32_t sAu = (uint32_t)__cvta_generic_to_shared(&sA[0][0]);
    const uint32_t sBu = (uint32_t)__cvta_generic_to_shared(&sB[0][0]);

    float4 arf[8];   // AMODE 1: 128*64 f32 = 2048 float4 / 256 thr
    uint4  arh[4];   // AMODE 2: 128*64 h = 1024 uint4 / 256 thr
    uint4  brh[2];   // NTILE*64 h = NTILE*8 uint4 / 256 thr (<=2)

    auto ldA = [&](int k0) {
        if (AMODE == 2) {
            #pragma unroll
            for (int j = 0; j < 4; ++j) {
                int it = tid + 256 * j;
                int r = it >> 3, q = it & 7;
                arh[j] = *reinterpret_cast<const uint4*>(
                    Ah + (size_t)(m0 + r) * Kd + k0 + q * 8);
            }
        } else {
            #pragma unroll
            for (int j = 0; j < 8; ++j) {
                int it = tid + 256 * j;
                int r = it >> 4, q = it & 15;
                arf[j] = *reinterpret_cast<const float4*>(
                    feats + (size_t)rowoff[r] * Kd + k0 + q * 4);
            }
        }
    };
    auto ldB = [&](int k0) {
        #pragma unroll
        for (int j = 0; j < 2; ++j) {
            int it = tid + 256 * j;
            if ((BQ % 512 == 0) || it < BQ) {
                int r = it >> 3, q = it & 7;
                brh[j] = *reinterpret_cast<const uint4*>(
                    Wh + (size_t)(n0 + r) * Kd + k0 + q * 8);
            }
        }
    };
    auto stA = [&](int buf) {
        if (AMODE == 2) {
            #pragma unroll
            for (int j = 0; j < 4; ++j) {
                int it = tid + 256 * j;
                int r = it >> 3, q = it & 7;
                *reinterpret_cast<uint4*>(&sA[buf][r * SA + q * 8]) = arh[j];
            }
        } else {
            #pragma unroll
            for (int j = 0; j < 8; ++j) {
                int it = tid + 256 * j;
                int r = it >> 4, q = it & 15;
                uint2 u = make_uint2(pack_half2(arf[j].x, arf[j].y),
                                     pack_half2(arf[j].z, arf[j].w));
                *reinterpret_cast<uint2*>(&sA[buf][r * SA + q * 4]) = u;
            }
        }
    };
    auto stB = [&](int buf) {
        #pragma unroll
        for (int j = 0; j < 2; ++j) {
            int it = tid + 256 * j;
            if ((BQ % 512 == 0) || it < BQ) {
                int r = it >> 3, q = it & 7;
                *reinterpret_cast<uint4*>(&sB[buf][r * SA + q * 8]) = brh[j];
            }
        }
    };

    float acc[mM][mN][4];
    #pragma unroll
    for (int i = 0; i < mM; ++i)
        #pragma unroll
        for (int j = 0; j < mN; ++j)
            #pragma unroll
            for (int q = 0; q < 4; ++q) acc[i][j][q] = 0.f;

    // ldmatrix lane-address components (in halves)
    const int a_row  = (lane & 15);
    const int a_koff = (lane >> 4) << 3;
    const int b_nrow = (lane & 7);
    const int b_tile = (lane >> 4);
    const int b_koff = ((lane >> 3) & 1) << 3;

    const int nc = Kd / KC;
    ldA(0); ldB(0);
    stA(0); stB(0);
    __syncthreads();

    for (int i = 0; i < nc; ++i) {
        const int buf = i & 1;
        if (i + 1 < nc) { ldA((i + 1) * KC); ldB((i + 1) * KC); }

        const uint32_t bAu = sAu + (uint32_t)buf * (128 * SA * 2);
        const uint32_t bBu = sBu + (uint32_t)buf * (NTILE * SA * 2);
        #pragma unroll
        for (int kk = 0; kk < KC; kk += 16) {
            uint32_t afr[mM][4];
            #pragma unroll
            for (int i2 = 0; i2 < mM; ++i2) {
                int rb = wm * RM + i2 * 16;
                uint32_t addr = bAu +
                    (uint32_t)((rb + a_row) * SA + kk + a_koff) * 2;
                ldmatrix_x4(afr[i2][0], afr[i2][1], afr[i2][2], afr[i2][3],
                            addr);
            }
            uint32_t bfr[mN][2];
            #pragma unroll
            for (int jp = 0; jp < mNP; ++jp) {
                int cb = wn * RN + jp * 16;
                uint32_t addr = bBu +
                    (uint32_t)((cb + b_tile * 8 + b_nrow) * SA + kk + b_koff) * 2;
                ldmatrix_x4(bfr[2*jp][0], bfr[2*jp][1],
                            bfr[2*jp+1][0], bfr[2*jp+1][1], addr);
            }
            #pragma unroll
            for (int i2 = 0; i2 < mM; ++i2)
                #pragma unroll
                for (int j2 = 0; j2 < mN; ++j2)
                    mma_fp16(acc[i2][j2], afr[i2], bfr[j2]);
        }

        if (i + 1 < nc) { stA(buf ^ 1); stB(buf ^ 1); __syncthreads(); }
    }

    // epilogue
    #pragma unroll
    for (int i2 = 0; i2 < mM; ++i2) {
        #pragma unroll
        for (int j2 = 0; j2 < mN; ++j2) {
            int row = m0 + wm * RM + i2 * 16 + g;
            int col = n0 + wn * RN + j2 * 8 + t * 2;
            float v0 = acc[i2][j2][0], v1 = acc[i2][j2][1];
            float v2 = acc[i2][j2][2], v3 = acc[i2][j2][3];
            if (BIAS) {
                float bc0 = bias[col], bc1 = bias[col + 1];
                v0 += bc0; v1 += bc1; v2 += bc0; v3 += bc1;
            }
            if (RESID) {
                v0 += resid[(size_t)row * N + col];
                v1 += resid[(size_t)row * N + col + 1];
                v2 += resid[(size_t)(row + 8) * N + col];
                v3 += resid[(size_t)(row + 8) * N + col + 1];
            }
            if (OUTHALF) {
                *reinterpret_cast<__half2*>(&Ch[(size_t)row * N + col]) =
                    __floats2half2_rn(v0, v1);
                *reinterpret_cast<__half2*>(&Ch[(size_t)(row + 8) * N + col]) =
                    __floats2half2_rn(v2, v3);
            } else {
                *reinterpret_cast<float2*>(&Cf[(size_t)row * N + col]) =
                    make_float2(v0, v1);
                *reinterpret_cast<float2*>(&Cf[(size_t)(row + 8) * N + col]) =
                    make_float2(v2, v3);
            }
        }
    }
}

// ---------- LayerNorm, warp-per-token (8 floats/lane, shfl-only) -------------
__global__ void ln_kernel(const float* __restrict__ x,
                          const float* __restrict__ gam,
                          const float* __restrict__ bet,
                          __half* __restrict__ xn)
{
    const int tok  = (blockIdx.x * blockDim.x + threadIdx.x) >> 5;
    const int lane = threadIdx.x & 31;
    const float* row = x + (size_t)tok * DM + lane * 8;

    float4 v0 = *reinterpret_cast<const float4*>(row);
    float4 v1 = *reinterpret_cast<const float4*>(row + 4);

    float s = v0.x + v0.y + v0.z + v0.w + v1.x + v1.y + v1.z + v1.w;
    #pragma unroll
    for (int o = 16; o; o >>= 1) s += __shfl_xor_sync(0xffffffffu, s, o);
    const float mu = s * (1.0f / DM);

    float d0 = v0.x - mu, d1 = v0.y - mu, d2 = v0.z - mu, d3 = v0.w - mu;
    float d4 = v1.x - mu, d5 = v1.y - mu, d6 = v1.z - mu, d7 = v1.w - mu;
    float q = d0*d0 + d1*d1 + d2*d2 + d3*d3 + d4*d4 + d5*d5 + d6*d6 + d7*d7;
    #pragma unroll
    for (int o = 16; o; o >>= 1) q += __shfl_xor_sync(0xffffffffu, q, o);
    const float rs = rsqrtf(q * (1.0f / DM) + 1e-5f);

    float4 g0 = *reinterpret_cast<const float4*>(gam + lane * 8);
    float4 g1 = *reinterpret_cast<const float4*>(gam + lane * 8 + 4);
    float4 b0 = *reinterpret_cast<const float4*>(bet + lane * 8);
    float4 b1 = *reinterpret_cast<const float4*>(bet + lane * 8 + 4);

    uint4 o4;
    *reinterpret_cast<__half2*>(&o4.x) =
        __floats2half2_rn(d0*rs*g0.x + b0.x, d1*rs*g0.y + b0.y);
    *reinterpret_cast<__half2*>(&o4.y) =
        __floats2half2_rn(d2*rs*g0.z + b0.z, d3*rs*g0.w + b0.w);
    *reinterpret_cast<__half2*>(&o4.z) =
        __floats2half2_rn(d4*rs*g1.x + b1.x, d5*rs*g1.y + b1.y);
    *reinterpret_cast<__half2*>(&o4.w) =
        __floats2half2_rn(d6*rs*g1.z + b1.z, d7*rs*g1.w + b1.w);
    *reinterpret_cast<uint4*>(xn + (size_t)tok * DM + lane * 8) = o4;
}

// ------- causal depthwise conv (width 4) + SiLU, fp16 in/out ----------------
__global__ void conv_kernel(const __half* __restrict__ xz,
                            const float* __restrict__ cw,
                            const float* __restrict__ cb,
                            __half* __restrict__ xc)
{
    int gi = blockIdx.x * 256 + threadIdx.x;  // over (NT/2)*(DI/4)
    if (gi >= (NT/2)*(DI/4)) return;
    int d4 = (gi & 127) << 2;
    int th = gi >> 7;
    int t0 = th << 1;
    int k0 = t0 & (KF-1);

    float4 w0 = *reinterpret_cast<const float4*>(cw + (d4+0)*4);
    float4 w1 = *reinterpret_cast<const float4*>(cw + (d4+1)*4);
    float4 w2 = *reinterpret_cast<const float4*>(cw + (d4+2)*4);
    float4 w3 = *reinterpret_cast<const float4*>(cw + (d4+3)*4);
    const float wj[4][4] = {
        {w0.x, w1.x, w2.x, w3.x},
        {w0.y, w1.y, w2.y, w3.y},
        {w0.z, w1.z, w2.z, w3.z},
        {w0.w, w1.w, w2.w, w3.w}};
    float4 bias4 = *reinterpret_cast<const float4*>(cb + d4);

    float4 tap[5];
    #pragma unroll
    for (int j = 0; j < 5; ++j) {
        int kk = k0 - 3 + j;
        if (kk >= 0) {
            uint2 u = *reinterpret_cast<const uint2*>(
                xz + (size_t)(t0 - 3 + j) * (2*DI) + d4);
            float2 f0 = __half22float2(*reinterpret_cast<__half2*>(&u.x));
            float2 f1 = __half22float2(*reinterpret_cast<__half2*>(&u.y));
            tap[j] = make_float4(f0.x, f0.y, f1.x, f1.y);
        } else {
            tap[j] = make_float4(0.f, 0.f, 0.f, 0.f);
        }
    }

    float4 a0 = bias4, a1 = bias4;
    #pragma unroll
    for (int j = 0; j < 4; ++j) {
        a0.x += wj[j][0] * tap[j].x;   a1.x += wj[j][0] * tap[j+1].x;
        a0.y += wj[j][1] * tap[j].y;   a1.y += wj[j][1] * tap[j+1].y;
        a0.z += wj[j][2] * tap[j].z;   a1.z += wj[j][2] * tap[j+1].z;
        a0.w += wj[j][3] * tap[j].w;   a1.w += wj[j][3] * tap[j+1].w;
    }
    float4 o0, o1;
    o0.x = a0.x / (1.f + __expf(-a0.x));  o1.x = a1.x / (1.f + __expf(-a1.x));
    o0.y = a0.y / (1.f + __expf(-a0.y));  o1.y = a1.y / (1.f + __expf(-a1.y));
    o0.z = a0.z / (1.f + __expf(-a0.z));  o1.z = a1.z / (1.f + __expf(-a1.z));
    o0.w = a0.w / (1.f + __expf(-a0.w));  o1.w = a1.w / (1.f + __expf(-a1.w));

    uint2 s0, s1;
    *reinterpret_cast<__half2*>(&s0.x) = __floats2half2_rn(o0.x, o0.y);
    *reinterpret_cast<__half2*>(&s0.y) = __floats2half2_rn(o0.z, o0.w);
    *reinterpret_cast<__half2*>(&s1.x) = __floats2half2_rn(o1.x, o1.y);
    *reinterpret_cast<__half2*>(&s1.y) = __floats2half2_rn(o1.z, o1.w);
    *reinterpret_cast<uint2*>(xc + (size_t)t0*DI + d4)     = s0;
    *reinterpret_cast<uint2*>(xc + (size_t)(t0+1)*DI + d4) = s1;
}

// ------- dt = softplus(dbl[:, :16] @ W_dt^T + b_dt) -> fp16 ------------------
__global__ void dt_kernel(const float* __restrict__ dbl,
                          const float* __restrict__ Wdt,
                          const float* __restrict__ bdt,
                          __half* __restrict__ dtout)
{
    __shared__ float s_dbl[64 * 16];
    const int tid = threadIdx.x;      // 256
    const int t0  = blockIdx.x * 64;

    float w0[16], w1[16];
    #pragma unroll
    for (int r = 0; r < 16; ++r) {
        w0[r] = Wdt[tid * 16 + r];
        w1[r] = Wdt[(tid + 256) * 16 + r];
    }
    const float b0 = bdt[tid], b1 = bdt[tid + 256];

    for (int i = tid; i < 64 * 16; i += 256) {
        int tt = i >> 4, r = i & 15;
        s_dbl[i] = dbl[(size_t)(t0 + tt) * 48 + r];
    }
    __syncthreads();

    for (int tt = 0; tt < 64; ++tt) {
        float a0 = b0, a1 = b1;
        #pragma unroll
        for (int r = 0; r < 16; ++r) {
            float v = s_dbl[tt * 16 + r];
            a0 += v * w0[r];
            a1 += v * w1[r];
        }
        size_t t = (size_t)(t0 + tt) * DI;
        float r0 = (a0 > 20.f) ? a0 : __logf(1.f + __expf(a0));
        float r1 = (a1 > 20.f) ? a1 : __logf(1.f + __expf(a1));
        dtout[t + tid]       = __float2half_rn(r0);
        dtout[t + tid + 256] = __float2half_rn(r1);
    }
}

// ---- selective scan: 8 lanes per d (2 states/lane), unroll 4, prefetch 4 ----
__global__ void scan_kernel(const __half* __restrict__ dt,
                            const __half* __restrict__ xc,
                            const float* __restrict__ dbl,
                            const __half* __restrict__ xz,
                            const float* __restrict__ Al,
                            const float* __restrict__ Dp,
                            __half* __restrict__ y)
{
    const int warp_gid = (blockIdx.x * blockDim.x + threadIdx.x) >> 5; // 0..2047
    const int lane = threadIdx.x & 31;
    const int g = lane >> 3;
    const int q = lane & 7;
    const int b = warp_gid >> 7;
    const int d = ((warp_gid & 127) << 2) + g;

    const float a0 = -__expf(Al[d*DS + 2*q + 0]);
    const float a1 = -__expf(Al[d*DS + 2*q + 1]);
    const float dp = Dp[d];

    bool fastl = fabsf(a0 + (float)(2*q+1)) < 1e-4f * (2*q+1)
              && fabsf(a1 + (float)(2*q+2)) < 1e-4f * (2*q+2);
    const bool fast = __all_sync(0xffffffffu, fastl);

    float h0 = 0.f, h1 = 0.f;
    const size_t tb = (size_t)b * KF;

    float  dtv[4], xcv[4], zv[4];
    float2 bm[4], cm[4];
    #pragma unroll
    for (int j = 0; j < 4; ++j) {
        const size_t t = tb + j;
        dtv[j] = __half2float(dt[t*DI + d]);
        xcv[j] = __half2float(xc[t*DI + d]);
        zv[j]  = __half2float(xz[t*(2*DI) + DI + d]);
        bm[j]  = *reinterpret_cast<const float2*>(dbl + t*48 + 16 + 2*q);
        cm[j]  = *reinterpret_cast<const float2*>(dbl + t*48 + 32 + 2*q);
    }

    for (int k = 0; k < KF; k += 4) {
        float  dtn[4], xcn[4], zvn[4];
        float2 bmn[4], cmn[4];
        #pragma unroll
        for (int j = 0; j < 4; ++j) {
            int kk = k + 4 + j; if (kk > KF-1) kk = KF-1;
            const size_t t = tb + kk;
            dtn[j] = __half2float(dt[t*DI + d]);
            xcn[j] = __half2float(xc[t*DI + d]);
            zvn[j] = __half2float(xz[t*(2*DI) + DI + d]);
            bmn[j] = *reinterpret_cast<const float2*>(dbl + t*48 + 16 + 2*q);
            cmn[j] = *reinterpret_cast<const float2*>(dbl + t*48 + 32 + 2*q);
        }

        float E[4];
        if (fast) {
            #pragma unroll
            for (int j = 0; j < 4; ++j) E[j] = __expf(-dtv[j]);
        }

        #pragma unroll
        for (int j = 0; j < 4; ++j) {
            float p0, p1;
            if (fast) {
                float e = E[j];
                float b2 = e*e;
                float b4 = b2*b2;
                float b8 = b4*b4;
                float pw = e;
                if (q & 1) pw *= b2;
                if (q & 2) pw *= b4;
                if (q & 4) pw *= b8;
                p0 = pw;
                p1 = pw * e;
            } else {
                p0 = __expf(dtv[j]*a0);
                p1 = __expf(dtv[j]*a1);
            }
            const float dtx = dtv[j] * xcv[j];
            h0 = p0*h0 + dtx*bm[j].x;
            h1 = p1*h1 + dtx*bm[j].y;
            float yp = h0*cm[j].x + h1*cm[j].y;
            yp += __shfl_xor_sync(0xffffffffu, yp, 1);
            yp += __shfl_xor_sync(0xffffffffu, yp, 2);
            yp += __shfl_xor_sync(0xffffffffu, yp, 4);
            if (q == 0) {
                float zs = zv[j] / (1.f + __expf(-zv[j]));
                y[(tb + k + j)*DI + d] = __float2half_rn((yp + dp*xcv[j]) * zs);
            }
        }
        #pragma unroll
        for (int j = 0; j < 4; ++j) {
            dtv[j] = dtn[j]; xcv[j] = xcn[j]; zv[j] = zvn[j];
            bm[j] = bmn[j]; cm[j] = cmn[j];
        }
    }
}

// ---------------- masked partial reduction over K ---------------------------
__global__ void reduce_kernel(const float* __restrict__ x,
                              const unsigned char* __restrict__ mask,
                              float* __restrict__ redp)
{
    const int b  = blockIdx.x;
    const int ch = blockIdx.y;
    const int m  = threadIdx.x;
    float acc = 0.f;
    const int kbeg = ch * 64;
    #pragma unroll 4
    for (int k = kbeg; k < kbeg + 64; ++k) {
        if (!mask[b*KF + k])
            acc += x[((size_t)b*KF + k)*DM + m];
    }
    redp[((size_t)b*16 + ch)*DM + m] = acc;
}

// ---------------- combine partials + output projection + mean ---------------
__global__ void final_kernel(const float* __restrict__ redp,
                             const unsigned char* __restrict__ mask,
                             const float* __restrict__ w_op,
                             const float* __restrict__ b_op,
                             float* __restrict__ out)
{
    const int b = blockIdx.x;
    const int o = threadIdx.x;
    __shared__ float s_r[DM];
    __shared__ int s_cnt;

    if (o == 0) s_cnt = 0;
    __syncthreads();

    int c = 0;
    #pragma unroll 4
    for (int k = o; k < KF; k += 256) c += mask[b*KF + k] ? 0 : 1;
    atomicAdd(&s_cnt, c);

    float acc = 0.f;
    #pragma unroll
    for (int ch = 0; ch < 16; ++ch) acc += redp[((size_t)b*16 + ch)*DM + o];
    s_r[o] = acc;
    __syncthreads();

    float cnt = fmaxf((float)s_cnt, 1.0f);
    float dot = 0.f;
    #pragma unroll 4
    for (int m = 0; m < DM; ++m) dot += s_r[m] * w_op[o*DM + m];
    out[(size_t)b*DOUT + o] = dot / cnt + b_op[o];
}

// ---------------- launch ----------------------------------------------------
extern "C" void kernel_launch(void* const* d_in, const int* in_sizes, int n_in,
                              void* d_out, int out_size)
{
    const float*         feats  = (const float*)d_in[0];
    const int*           idx    = (const int*)d_in[1];
    const unsigned char* mask   = (const unsigned char*)d_in[2];
    const float* w_ip   = (const float*)d_in[3];
    const float* b_ip   = (const float*)d_in[4];
    const float* ln_g   = (const float*)d_in[5];
    const float* ln_b   = (const float*)d_in[6];
    const float* W_in   = (const float*)d_in[7];
    const float* conv_w = (const float*)d_in[8];
    const float* conv_b = (const float*)d_in[9];
    const float* W_xp   = (const float*)d_in[10];
    const float* W_dt   = (const float*)d_in[11];
    const float* b_dt   = (const float*)d_in[12];
    const float* A_log  = (const float*)d_in[13];
    const float* Dp     = (const float*)d_in[14];
    const float* W_out  = (const float*)d_in[15];
    const float* w_op   = (const float*)d_in[16];
    const float* b_op   = (const float*)d_in[17];
    float* out = (float*)d_out;

    float *x, *dbl, *redp;
    __half *xn, *xz, *xc, *dt, *y, *wh;
    cudaGetSymbolAddress((void**)&x,    g_x);
    cudaGetSymbolAddress((void**)&xn,   g_xn);
    cudaGetSymbolAddress((void**)&xz,   g_xz);
    cudaGetSymbolAddress((void**)&xc,   g_xc);
    cudaGetSymbolAddress((void**)&dbl,  g_dbl);
    cudaGetSymbolAddress((void**)&dt,   g_dt);
    cudaGetSymbolAddress((void**)&y,    g_y);
    cudaGetSymbolAddress((void**)&redp, g_redp);
    cudaGetSymbolAddress((void**)&wh,   g_wh);

    // --- pre-convert all GEMM weights to fp16 in ONE launch ---
    f2h_all_kernel<<<(WH_TOTAL/4 + 255)/256, 256>>>(
        w_ip, W_in, W_xp, W_out, wh);

    // input projection with fused keyframe gather: x (fp32)
    gemm_h<64, 2, 1, true, false, false><<<dim3(DM/64, NT/128), 256>>>(
        nullptr, wh + WH_IP, x, nullptr, DM, DIN,
        b_ip, nullptr, feats, idx);

    for (int l = 0; l < NL; ++l) {
        ln_kernel<<<NT/8, 256>>>(x, ln_g + l*DM, ln_b + l*DM, xn);

        // xz = xn @ W_in^T  (fp16 in/out, fp16 weights)
        gemm_h<64, 2, 2, false, false, true>
            <<<dim3(2*DI/64, NT/128), 256>>>(
            xn, wh + WH_IN + (size_t)l*2*DI*DM, nullptr, xz, 2*DI, DM,
            nullptr, nullptr, nullptr, nullptr);

        conv_kernel<<<((NT/2)*(DI/4))/256, 256>>>(
            xz, conv_w + (size_t)l*DI*DCONV, conv_b + (size_t)l*DI, xc);

        // dbl = xc @ W_xp^T  (fp16 in, fp32 out), N=48
        gemm_h<48, 1, 2, false, false, false>
            <<<dim3(1, NT/128), 256>>>(
            xc, wh + WH_XP + (size_t)l*48*DI, dbl, nullptr, 48, DI,
            nullptr, nullptr, nullptr, nullptr);

        // dt = softplus(dbl[:, :16] @ W_dt^T + b_dt) -> fp16
        dt_kernel<<<NT/64, 256>>>(
            dbl, W_dt + (size_t)l*DI*DTR, b_dt + (size_t)l*DI, dt);

        // scan: 2048 warps = 256 blocks x 256 threads
        scan_kernel<<<256, 256>>>(
            dt, xc, dbl, xz, A_log + (size_t)l*DI*DS, Dp + (size_t)l*DI, y);

        // x = y @ W_out^T + x  (fp16 A/weights, fp32 resid/out)
        gemm_h<64, 2, 2, false, true, false>
            <<<dim3(DM/64, NT/128), 256>>>(
            y, wh + WH_OUT + (size_t)l*DM*DI, x, nullptr, DM, DI,
            nullptr, x, nullptr, nullptr);
    }

    reduce_kernel<<<dim3(B_, 16), 256>>>(x, mask, redp);
    final_kernel<<<B_, 256>>>(redp, mask, w_op, b_op, out);
}